// round 2
// baseline (speedup 1.0000x reference)
#include <cuda_runtime.h>

// ---------------------------------------------------------------------------
// GroupedQueryAttention, restructured:
//   x_embed affine in scalar x[b,s] => K[b,s,j] = x*kwf[j] + kc[s,j]
//   score (log2 domain) = a[g,p]*x[b,s] + bconst[g,p,s]   (exp2-safe, no max)
//   ctx = invZ * ( sum_s e*vc[s,:] + (sum_s e*x) * vw )
//   out = ctx @ o_w + o_b
// Pair p in [0,32) per group g: r=p>>3, q=p&7, head h=g*4+r.
// k_main: 1024-thr CTA, 32 warps; warp w handles pairs (2*(w&15), +1) over
// s-half (w>>4); halves combine via smem. Grid (74,2) = one full wave.
// ---------------------------------------------------------------------------

#define LOG2E_OVER_SCALE ((float)(1.4426950408889634 / 2.8284271247461903))

__device__ __align__(16) float g_bconst[2][16][1024][2];  // [g][wp][s][pair01] 256 KB
__device__ __align__(16) float g_vc2f[2][4][1024][2];     // [g][jj][s]{lo,hi}  64 KB
__device__ float g_a[2][32];
__device__ float g_vw[2][8];
__device__ __align__(16) float g_ctx[1024][8][64];        // 2 MB scratch

__device__ __forceinline__ float ex2f(float x) {
    float r; asm("ex2.approx.ftz.f32 %0, %1;" : "=f"(r) : "f"(x)); return r;
}
__device__ __forceinline__ unsigned long long pack2(float a, float b) {
    unsigned long long r; asm("mov.b64 %0, {%1, %2};" : "=l"(r) : "f"(a), "f"(b)); return r;
}
__device__ __forceinline__ void unpack2(unsigned long long v, float& a, float& b) {
    asm("mov.b64 {%0, %1}, %2;" : "=f"(a), "=f"(b) : "l"(v));
}
__device__ __forceinline__ void fma2(unsigned long long& d, unsigned long long a, unsigned long long b) {
    asm("fma.rn.f32x2 %0, %1, %2, %0;" : "+l"(d) : "l"(a), "l"(b));
}
__device__ __forceinline__ float wsum(float v) {
#pragma unroll
    for (int m = 16; m > 0; m >>= 1) v += __shfl_xor_sync(0xffffffffu, v, m);
    return v;
}

// --- precompute 1: a[g][p] (x-coefficient of logits), vw -------------------
__global__ void k_pre1(const float* __restrict__ fe_w, const float* __restrict__ k_w,
                       const float* __restrict__ v_w, const float* __restrict__ queries) {
    __shared__ float kw[16];
    int t = threadIdx.x;  // 64 threads
    if (t < 16) {
        float sk = 0.f, sv = 0.f;
        for (int d = 0; d < 64; d++) {
            sk = fmaf(fe_w[d], k_w[d * 16 + t], sk);
            sv = fmaf(fe_w[d], v_w[d * 16 + t], sv);
        }
        kw[t] = sk;
        g_vw[t >> 3][t & 7] = sv;
    }
    __syncthreads();
    int g = t >> 5, p = t & 31, r = p >> 3, q = p & 7, h = g * 4 + r;
    float s = 0.f;
#pragma unroll
    for (int j = 0; j < 8; j++) s = fmaf(queries[q * 64 + h * 8 + j], kw[g * 8 + j], s);
    g_a[g][p] = s * LOG2E_OVER_SCALE;
}

// --- precompute 2 (fused): kc/vc per s, then bconst ------------------------
__global__ __launch_bounds__(256) void k_pre2(
        const float* __restrict__ fe_b, const float* __restrict__ pos_emb,
        const float* __restrict__ k_w, const float* __restrict__ k_b,
        const float* __restrict__ v_w, const float* __restrict__ v_b,
        const float* __restrict__ queries) {
    __shared__ float sk[16][16];   // kc for 16 local s
    int t = threadIdx.x;
    int s0 = blockIdx.x * 16;
    {   // phase 1: (s_local, j) per thread
        int sl = t >> 4, j = t & 15;
        int s = s0 + sl;
        float kc = k_b[j], vc = v_b[j];
        for (int d = 0; d < 64; d++) {
            float e = fe_b[d] + pos_emb[s * 64 + d];
            kc = fmaf(e, k_w[d * 16 + j], kc);
            vc = fmaf(e, v_w[d * 16 + j], vc);
        }
        sk[sl][j] = kc;
        g_vc2f[j >> 3][(j & 7) >> 1][s][j & 1] = vc;
    }
    __syncthreads();
    // phase 2: 16 s * 64 pairs = 1024 items, 4 per thread
#pragma unroll
    for (int u = 0; u < 4; u++) {
        int item = t + 256 * u;
        int sl = item >> 6, pp = item & 63;
        int g = pp >> 5, p = pp & 31, r = p >> 3, q = p & 7, h = g * 4 + r;
        float acc = 0.f;
#pragma unroll
        for (int j = 0; j < 8; j++) acc = fmaf(queries[q * 64 + h * 8 + j], sk[sl][g * 8 + j], acc);
        g_bconst[g][p >> 1][s0 + sl][p & 1] = acc * LOG2E_OVER_SCALE;
    }
}

// --- main: softmax + attn store + ctx ---------------------------------------
__global__ __launch_bounds__(1024, 1) void k_main(const float* __restrict__ x,
                                                  float* __restrict__ attn_out) {
    extern __shared__ float smem[];
    float2* sm_b = (float2*)smem;                                     // [16][1024] f2 = 128KB
    unsigned long long* sm_vc = (unsigned long long*)(smem + 32768);  // [4][1024]  = 32KB
    float* sm_x = smem + 32768 + 8192;                                // 1024 floats
    float* sm_red = sm_x + 1024;                                      // 32*20 floats
    const int g = blockIdx.y;
    const int tid = threadIdx.x;

    {   // cache group tables in smem once per CTA
        const float4* src = (const float4*)&g_bconst[g][0][0][0];
        float4* dst = (float4*)smem;
#pragma unroll
        for (int i = 0; i < 8; i++) dst[tid + 1024 * i] = src[tid + 1024 * i];
        const float4* vs = (const float4*)&g_vc2f[g][0][0][0];
        float4* vd = (float4*)(smem + 32768);
#pragma unroll
        for (int i = 0; i < 2; i++) vd[tid + 1024 * i] = vs[tid + 1024 * i];
    }

    const int w = tid >> 5, lane = tid & 31;
    const int wp = w & 15, half = w >> 4;
    const int p0 = 2 * wp, p1 = p0 + 1;
    const float a0 = g_a[g][p0], a1 = g_a[g][p1];
    const int h0 = g * 4 + (p0 >> 3), q0 = p0 & 7;
    const int h1 = g * 4 + (p1 >> 3), q1 = p1 & 7;
    const int sbase = half * 512 + lane;

    for (int b = blockIdx.x; b < 1024; b += 74) {
        __syncthreads();   // protects sm_x and sm_red reuse
        sm_x[tid] = x[b * 1024 + tid];
        __syncthreads();

        float eA[16], eB[16];
        float z0 = 0.f, z1 = 0.f, xs0 = 0.f, xs1 = 0.f;
        unsigned long long c0[4], c1[4];
#pragma unroll
        for (int k = 0; k < 4; k++) { c0[k] = 0ull; c1[k] = 0ull; }

#pragma unroll
        for (int i = 0; i < 16; i++) {
            int s = sbase + i * 32;
            float xv = sm_x[s];
            float2 bb = sm_b[wp * 1024 + s];
            float e0 = ex2f(fmaf(a0, xv, bb.x));
            float e1 = ex2f(fmaf(a1, xv, bb.y));
            eA[i] = e0; eB[i] = e1;
            z0 += e0; z1 += e1;
            xs0 = fmaf(e0, xv, xs0); xs1 = fmaf(e1, xv, xs1);
            unsigned long long pe0 = pack2(e0, e0), pe1 = pack2(e1, e1);
#pragma unroll
            for (int k = 0; k < 4; k++) {
                unsigned long long vv = sm_vc[k * 1024 + s];
                fma2(c0[k], pe0, vv);
                fma2(c1[k], pe1, vv);
            }
        }

        z0 = wsum(z0); z1 = wsum(z1); xs0 = wsum(xs0); xs1 = wsum(xs1);
        float cf0[8], cf1[8];
#pragma unroll
        for (int k = 0; k < 4; k++) {
            unpack2(c0[k], cf0[2 * k], cf0[2 * k + 1]);
            unpack2(c1[k], cf1[2 * k], cf1[2 * k + 1]);
        }
#pragma unroll
        for (int j = 0; j < 8; j++) { cf0[j] = wsum(cf0[j]); cf1[j] = wsum(cf1[j]); }

        if (lane == 0) {
            float* r = sm_red + w * 20;
            r[0] = z0; r[1] = xs0;
#pragma unroll
            for (int j = 0; j < 8; j++) r[2 + j] = cf0[j];
            r[10] = z1; r[11] = xs1;
#pragma unroll
            for (int j = 0; j < 8; j++) r[12 + j] = cf1[j];
        }
        __syncthreads();

        const float* rm = sm_red + w * 20;
        const float* rp = sm_red + (w ^ 16) * 20;
        float invZ0 = 1.0f / (rm[0] + rp[0]);
        float invZ1 = 1.0f / (rm[10] + rp[10]);

        if (half == 0 && lane < 16) {
            int pr = lane >> 3, j = lane & 7;
            int off = pr * 10;
            float xst = rm[1 + off] + rp[1 + off];
            float cft = rm[2 + off + j] + rp[2 + off + j];
            float iz = pr ? invZ1 : invZ0;
            int q = pr ? q1 : q0, h = pr ? h1 : h0;
            g_ctx[b][q][h * 8 + j] = iz * fmaf(xst, g_vw[g][j], cft);
        }

        float* o0 = attn_out + (((size_t)b * 8 + h0) * 8 + q0) * 1024 + sbase;
        float* o1 = attn_out + (((size_t)b * 8 + h1) * 8 + q1) * 1024 + sbase;
#pragma unroll
        for (int i = 0; i < 16; i++) {
            o0[i * 32] = eA[i] * invZ0;
            o1[i * 32] = eB[i] * invZ1;
        }
    }
}

// --- epilogue: out = ctx @ o_w + o_b -----------------------------------------
__global__ __launch_bounds__(512) void k_epilogue(const float* __restrict__ o_w,
                                                  const float* __restrict__ o_b,
                                                  float* __restrict__ out) {
    __shared__ float sw[4096];   // o_w tile 64x64
    __shared__ float sc[512];
    int b = blockIdx.x, t = threadIdx.x;
#pragma unroll
    for (int i = 0; i < 8; i++) sw[t + 512 * i] = o_w[t + 512 * i];
    sc[t] = ((const float*)g_ctx)[b * 512 + t];
    __syncthreads();
    int q = t >> 6, e = t & 63;
    float acc = o_b[e];
#pragma unroll
    for (int f = 0; f < 64; f++) acc = fmaf(sc[q * 64 + f], sw[f * 64 + e], acc);
    out[(size_t)b * 512 + t] = acc;
}

// ---------------------------------------------------------------------------
extern "C" void kernel_launch(void* const* d_in, const int* in_sizes, int n_in,
                              void* d_out, int out_size) {
    const float* x       = (const float*)d_in[0];
    const float* queries = (const float*)d_in[1];
    const float* fe_w    = (const float*)d_in[2];
    const float* fe_b    = (const float*)d_in[3];
    const float* pos_emb = (const float*)d_in[4];
    const float* k_w     = (const float*)d_in[5];
    const float* k_b     = (const float*)d_in[6];
    const float* v_w     = (const float*)d_in[7];
    const float* v_b     = (const float*)d_in[8];
    const float* o_w     = (const float*)d_in[9];
    const float* o_b     = (const float*)d_in[10];

    float* out  = (float*)d_out;                 // [1024, 512]
    float* attn = out + 1024 * 512;              // [1024, 8, 8, 1024]

    int smem_bytes = (32768 + 8192 + 1024 + 640) * 4;  // 170,496 B
    cudaFuncSetAttribute(k_main, cudaFuncAttributeMaxDynamicSharedMemorySize, smem_bytes);

    k_pre1<<<1, 64>>>(fe_w, k_w, v_w, queries);
    k_pre2<<<64, 256>>>(fe_b, pos_emb, k_w, k_b, v_w, v_b, queries);
    k_main<<<dim3(74, 2), 1024, smem_bytes>>>(x, attn);
    k_epilogue<<<1024, 512>>>(o_w, o_b, out);
}